// round 14
// baseline (speedup 1.0000x reference)
#include <cuda_runtime.h>
#include <cuda_bf16.h>
#include <cstdint>

#define BB   16
#define DD   64
#define LL   2048
#define KK   1000
#define KPAD 1024
#define NN   (BB * LL)             // 32768 tokens
#define TM2  256                   // tokens per CTA
#define KC   128                   // codes per chunk
#define NCHUNK 8
#define NBLK (NN / TM2)            // 128 CTAs
#define THREADS 256

#define OUT_ELEMS (BB * DD * LL)
#define LOSS_OFF  OUT_ELEMS
#define USAGE_OFF (OUT_ELEMS + 1)
#define IDX_OFF   (OUT_ELEMS + 2)

// Fragment-major SMEM layout.
// A frags: [pa(3)][st(16)][ks(4)][lane(32)] x 16B = 98304
// B frags: [buf(2)][pb(3)][ng(16)][ks(4)][lane(32)] x 8B = 2 x 49152
#define SM_AF    0
#define AF_PA    32768                 // bytes per pa block
#define SM_B     98304
#define B_CHUNK  49152
#define B_PB     16384
#define SM_SE    196608                // float[1024] code norms
#define SM_XN    200704                // float[256] token norms
#define SM_RV    201728                // float[256][2]
#define SM_RI    203776                // int[256][2]
#define SM_II    205824                // int[256]
#define SM_LS    206848                // float[8]
#define SM_TOTAL 206880

__device__ __align__(16) unsigned short g_esplit[NCHUNK][3 * KC * DD];
__device__ float g_enorm[KPAD];
__device__ float g_partial[NBLK];
__device__ int   g_flags[KK];
__device__ int   g_done;

// ---------------- helpers ----------------
__device__ __forceinline__ uint32_t smem_u32(const void* p) {
    uint32_t a;
    asm("{ .reg .u64 t; cvta.to.shared.u64 t, %1; cvt.u32.u64 %0, t; }"
        : "=r"(a) : "l"(p));
    return a;
}
__device__ __forceinline__ void sts32(uint32_t a, uint32_t v) {
    asm volatile("st.shared.b32 [%0], %1;" :: "r"(a), "r"(v) : "memory");
}
__device__ __forceinline__ void lds64(uint32_t& lo, uint32_t& hi, uint32_t a) {
    asm("ld.shared.v2.u32 {%0, %1}, [%2];" : "=r"(lo), "=r"(hi) : "r"(a));
}
__device__ __forceinline__ void lds128(uint32_t* r, uint32_t a) {
    asm("ld.shared.v4.u32 {%0, %1, %2, %3}, [%4];"
        : "=r"(r[0]), "=r"(r[1]), "=r"(r[2]), "=r"(r[3]) : "r"(a));
}
__device__ __forceinline__ void mma16816(float* c, const uint32_t* a,
                                         uint32_t b0, uint32_t b1) {
    asm volatile("mma.sync.aligned.m16n8k16.row.col.f32.bf16.bf16.f32 "
                 "{%0,%1,%2,%3}, {%4,%5,%6,%7}, {%8,%9}, {%0,%1,%2,%3};"
                 : "+f"(c[0]), "+f"(c[1]), "+f"(c[2]), "+f"(c[3])
                 : "r"(a[0]), "r"(a[1]), "r"(a[2]), "r"(a[3]),
                   "r"(b0), "r"(b1));
}
#define CP_ASYNC16(dst, src) \
    asm volatile("cp.async.cg.shared.global [%0], [%1], 16;" \
                 :: "r"(dst), "l"(src) : "memory")
#define CP_COMMIT() asm volatile("cp.async.commit_group;" ::: "memory")
#define CP_WAIT0()  asm volatile("cp.async.wait_group 0;" ::: "memory")

// ---- prep: 3-way bf16 split of codebook, written FRAGMENT-MAJOR ----
__global__ void __launch_bounds__(256, 4)
vq_prep(const float* __restrict__ emb) {
    __shared__ float hsum[8];
    int tid = threadIdx.x;
    int idx = blockIdx.x * 256 + tid;
    int k = idx >> 6, d = idx & 63;
    float e = (k < KK) ? emb[(size_t)k * DD + d] : 0.0f;

    float pn = e * e;
    #pragma unroll
    for (int off = 16; off > 0; off >>= 1)
        pn += __shfl_xor_sync(0xffffffffu, pn, off);
    if ((tid & 31) == 0) hsum[tid >> 5] = pn;

    __nv_bfloat16 b1 = __float2bfloat16(e);
    float r1 = e - __bfloat162float(b1);
    __nv_bfloat16 b2 = __float2bfloat16(r1);
    __nv_bfloat16 b3 = __float2bfloat16(r1 - __bfloat162float(b2));
    unsigned short vals[3] = { __bfloat16_as_ushort(b1),
                               __bfloat16_as_ushort(b2),
                               __bfloat16_as_ushort(b3) };

    // fragment position: n = lane>>2 within ng, k = (lane&3)*2 {+0,+1} (+8 for b1 reg)
    int ch = k >> 7, kc = k & 127;
    int ng = kc >> 3, nq = kc & 7;
    int ks = d >> 4, r = d & 15;
    int regsel = (r >= 8) ? 1 : 0;
    int lr = (r & 7) >> 1;
    int half = r & 1;
    int lane = nq * 4 + lr;
    int u16idx = ((ng * 4 + ks) * 32 + lane) * 4 + regsel * 2 + half;
    unsigned short* base = &g_esplit[ch][0];
    #pragma unroll
    for (int pb = 0; pb < 3; pb++)
        base[pb * 8192 + u16idx] = vals[pb];

    __syncthreads();
    if (tid < 4) {
        int kk2 = blockIdx.x * 4 + tid;
        g_enorm[kk2] = (kk2 < KK) ? (hsum[2 * tid] + hsum[2 * tid + 1]) : 3.4e38f;
    }
}

// One pipelined (product,kstep) iteration. AC: current A frags (uint4[4]),
// AN: next-iteration A frags (loaded via LDS.128, interleaved at nt<4).
// B fragments batched as 8 LDS.64 at iteration top.
#define STEP(AC, AN, IT) do {                                               \
    const int p_ = (IT) >> 2;                                               \
    const int ks_ = (IT) & 3;                                               \
    const int pb_ = (p_ < 3) ? 0 : ((p_ < 5) ? 1 : 2);                      \
    const uint32_t bb_ = bLane + (uint32_t)pb_ * B_PB + (uint32_t)ks_ * 256u;\
    const int itn_ = (IT) + 1;                                              \
    const int pn_ = itn_ >> 2;                                              \
    const int ksn_ = itn_ & 3;                                              \
    const int pan_ = (pn_ < 3) ? pn_ : ((pn_ < 5) ? pn_ - 3 : 0);           \
    const uint32_t an_ = aLane + (uint32_t)pan_ * AF_PA + (uint32_t)ksn_ * 512u;\
    uint32_t b0_[8], b1_[8];                                                \
    _Pragma("unroll")                                                       \
    for (int nt_ = 0; nt_ < 8; nt_++)                                       \
        lds64(b0_[nt_], b1_[nt_], bb_ + nt_ * 1024u);                       \
    _Pragma("unroll")                                                       \
    for (int nt_ = 0; nt_ < 8; nt_++) {                                     \
        if (nt_ < 4 && itn_ < 24)                                           \
            lds128((uint32_t*)&AN[nt_], an_ + nt_ * 2048u);                 \
        mma16816(acc[0][nt_], (const uint32_t*)&AC[0], b0_[nt_], b1_[nt_]); \
        mma16816(acc[1][nt_], (const uint32_t*)&AC[1], b0_[nt_], b1_[nt_]); \
        mma16816(acc[2][nt_], (const uint32_t*)&AC[2], b0_[nt_], b1_[nt_]); \
        mma16816(acc[3][nt_], (const uint32_t*)&AC[3], b0_[nt_], b1_[nt_]); \
    }                                                                       \
} while (0)

// ---- main: HMMA split-GEMM + argmin + gather + loss + fused finalize ----
__global__ void __launch_bounds__(THREADS, 1)
vq_main(const float* __restrict__ x, const float* __restrict__ emb,
        float* __restrict__ dout) {
    extern __shared__ char smem[];
    const uint32_t sb = smem_u32(smem);
    float* se  = (float*)(smem + SM_SE);
    float* xns = (float*)(smem + SM_XN);
    float* rv2 = (float*)(smem + SM_RV);
    int*   ri2 = (int*)(smem + SM_RI);
    int*   ii  = (int*)(smem + SM_II);
    float* ls  = (float*)(smem + SM_LS);
    __shared__ int amlast;
    __shared__ int cnt_s;

    const int tid  = threadIdx.x;
    const int warp = tid >> 5;
    const int lane = tid & 31;
    const int wm   = warp & 3;     // m-slice (64 tokens)
    const int wn   = warp >> 2;    // n-slice (64 codes)
    const int lq   = lane >> 2;    // 0..7
    const int lr   = lane & 3;     // 0..3
    const int b    = blockIdx.x >> 3;
    const int l0   = (blockIdx.x & 7) * TM2;

    // Start B chunk-0 copy early (linear, fully coalesced)
    {
        const char* src = (const char*)&g_esplit[0][0];
        uint32_t dstb = sb + SM_B;
        #pragma unroll
        for (int i = tid; i < B_CHUNK / 16; i += THREADS)
            CP_ASYNC16(dstb + i * 16, src + i * 16);
        CP_COMMIT();
    }

    // A build: thread owns token t = tid; scatter splits into fragment layout
    {
        const float* xp = x + (size_t)b * DD * LL + l0 + tid;
        const int rr = tid & 15, st = tid >> 4;
        const int regm = (rr >= 8) ? 1 : 0;
        float xn = 0.0f;
        #pragma unroll 4
        for (int d = 0; d < DD; d += 2) {
            float v0 = xp[(size_t)d * LL];
            float v1 = xp[(size_t)(d + 1) * LL];
            xn += v0 * v0 + v1 * v1;
            __nv_bfloat16 a1 = __float2bfloat16(v0);
            float r = v0 - __bfloat162float(a1);
            __nv_bfloat16 a2 = __float2bfloat16(r);
            __nv_bfloat16 a3 = __float2bfloat16(r - __bfloat162float(a2));
            __nv_bfloat16 c1 = __float2bfloat16(v1);
            float q = v1 - __bfloat162float(c1);
            __nv_bfloat16 c2 = __float2bfloat16(q);
            __nv_bfloat16 c3 = __float2bfloat16(q - __bfloat162float(c2));
            int ks = d >> 4, dr = d & 15;
            int reg = regm + ((dr >= 8) ? 2 : 0);
            int lw  = (rr & 7) * 4 + ((dr & 7) >> 1);
            uint32_t addr = sb + SM_AF + (uint32_t)((st * 4 + ks) * 32 + lw) * 16u
                          + (uint32_t)reg * 4u;
            sts32(addr,            (uint32_t)__bfloat16_as_ushort(a1) |
                                   ((uint32_t)__bfloat16_as_ushort(c1) << 16));
            sts32(addr + AF_PA,    (uint32_t)__bfloat16_as_ushort(a2) |
                                   ((uint32_t)__bfloat16_as_ushort(c2) << 16));
            sts32(addr + 2*AF_PA,  (uint32_t)__bfloat16_as_ushort(a3) |
                                   ((uint32_t)__bfloat16_as_ushort(c3) << 16));
        }
        xns[tid] = xn;
    }
    for (int i = tid; i < KPAD; i += THREADS) se[i] = g_enorm[i];

    CP_WAIT0();
    __syncthreads();

    float bestv[8];
    int   besti[8];
    #pragma unroll
    for (int s = 0; s < 8; s++) { bestv[s] = 3.0e38f; besti[s] = 0; }

    // per-thread fragment bases
    const uint32_t aLane = sb + SM_AF + (uint32_t)(wm * 4) * 2048u + lane * 16u;
    const uint32_t bBase = sb + SM_B + (uint32_t)(wn * 8) * 1024u + lane * 8u;

    for (int c = 0; c < NCHUNK; c++) {
        const uint32_t bLane = bBase + (uint32_t)(c & 1) * B_CHUNK;
        if (c + 1 < NCHUNK) {
            const char* src = (const char*)&g_esplit[c + 1][0];
            uint32_t dstb = sb + SM_B + ((c + 1) & 1) * B_CHUNK;
            #pragma unroll
            for (int i = tid; i < B_CHUNK / 16; i += THREADS)
                CP_ASYNC16(dstb + i * 16, src + i * 16);
            CP_COMMIT();
        }

        float acc[4][8][4];
        #pragma unroll
        for (int mt = 0; mt < 4; mt++)
            #pragma unroll
            for (int nt = 0; nt < 8; nt++)
                #pragma unroll
                for (int r = 0; r < 4; r++) acc[mt][nt][r] = 0.0f;

        uint4 acur[4], anx[4];
        #pragma unroll
        for (int mt = 0; mt < 4; mt++)         // it=0: pa=0, ks=0
            lds128((uint32_t*)&acur[mt], aLane + mt * 2048u);

        #pragma unroll 2
        for (int it = 0; it < 24; it += 2) {
            STEP(acur, anx, it);
            STEP(anx, acur, it + 1);
        }

        // Argmin on this chunk's distances
        #pragma unroll
        for (int nt = 0; nt < 8; nt++) {
            int cbase = c * KC + wn * 64 + nt * 8 + lr * 2;
            float2 en = *(const float2*)(se + cbase);
            #pragma unroll
            for (int mt = 0; mt < 4; mt++) {
                #pragma unroll
                for (int h = 0; h < 2; h++) {
                    int s = mt * 2 + h;
                    float m0 = fmaf(-2.0f, acc[mt][nt][2 * h],     en.x);
                    float m1 = fmaf(-2.0f, acc[mt][nt][2 * h + 1], en.y);
                    if (m0 < bestv[s] || (m0 == bestv[s] && cbase < besti[s]))
                        { bestv[s] = m0; besti[s] = cbase; }
                    if (m1 < bestv[s] || (m1 == bestv[s] && cbase + 1 < besti[s]))
                        { bestv[s] = m1; besti[s] = cbase + 1; }
                }
            }
        }

        CP_WAIT0();
        __syncthreads();
    }

    // Reduce across the 4 lanes (lr) sharing each token row
    #pragma unroll
    for (int s = 0; s < 8; s++) {
        #pragma unroll
        for (int off = 1; off <= 2; off <<= 1) {
            float ov = __shfl_xor_sync(0xffffffffu, bestv[s], off);
            int   oi = __shfl_xor_sync(0xffffffffu, besti[s], off);
            if (ov < bestv[s] || (ov == bestv[s] && oi < besti[s]))
                { bestv[s] = ov; besti[s] = oi; }
        }
    }
    if (lr == 0) {
        #pragma unroll
        for (int mt = 0; mt < 4; mt++)
            #pragma unroll
            for (int h = 0; h < 2; h++) {
                int t = wm * 64 + mt * 16 + lq + 8 * h;
                rv2[t * 2 + wn] = bestv[mt * 2 + h];
                ri2[t * 2 + wn] = besti[mt * 2 + h];
            }
    }
    __syncthreads();

    // Final per-token merge + outputs
    {
        float bv = rv2[tid * 2];
        int   bi = ri2[tid * 2];
        float v  = rv2[tid * 2 + 1];
        int   ix = ri2[tid * 2 + 1];
        if (v < bv || (v == bv && ix < bi)) { bv = v; bi = ix; }
        dout[IDX_OFF + b * LL + l0 + tid] = (float)bi;
        ii[tid] = bi;
        g_flags[bi] = 1;
        float sd = xns[tid] + bv;
        #pragma unroll
        for (int off = 16; off > 0; off >>= 1)
            sd += __shfl_down_sync(0xffffffffu, sd, off);
        if (lane == 0) ls[warp] = sd;
    }
    __syncthreads();
    if (tid == 0) {
        float s = 0.0f;
        #pragma unroll
        for (int w = 0; w < 8; w++) s += ls[w];
        g_partial[blockIdx.x] = s;
    }

    // Gather + transpose write (coalesced stores)
    for (int i = tid; i < DD * TM2; i += THREADS) {
        int d = i >> 8, t = i & 255;
        dout[((size_t)(b * DD + d)) * LL + l0 + t] = emb[(size_t)ii[t] * DD + d];
    }

    // ---- fused finalize: last CTA reduces loss + usage, resets state ----
    __threadfence();
    if (tid == 0) {
        int old = atomicAdd(&g_done, 1);
        amlast = (old == NBLK - 1) ? 1 : 0;
        cnt_s = 0;
    }
    __syncthreads();
    if (amlast) {
        __threadfence();
        float s = (tid < NBLK) ? g_partial[tid] : 0.0f;
        #pragma unroll
        for (int off = 16; off > 0; off >>= 1)
            s += __shfl_down_sync(0xffffffffu, s, off);
        if (lane == 0) ls[warp] = s;

        int f = 0;
        for (int i = tid; i < KK; i += THREADS) {
            f += g_flags[i];
            g_flags[i] = 0;
        }
        #pragma unroll
        for (int off = 16; off > 0; off >>= 1)
            f += __shfl_down_sync(0xffffffffu, f, off);
        if (lane == 0) atomicAdd(&cnt_s, f);
        __syncthreads();
        if (tid == 0) {
            float lsum = 0.0f;
            #pragma unroll
            for (int w = 0; w < 8; w++) lsum += ls[w];
            dout[LOSS_OFF]  = 11.0f * lsum / (float)(NN * DD);
            dout[USAGE_OFF] = (float)cnt_s;
            g_done = 0;
            __threadfence();
        }
    }
}

extern "C" void kernel_launch(void* const* d_in, const int* in_sizes, int n_in,
                              void* d_out, int out_size) {
    (void)n_in; (void)out_size;
    const float* x;
    const float* emb;
    if (in_sizes[0] == KK * DD) { emb = (const float*)d_in[0]; x = (const float*)d_in[1]; }
    else                        { x   = (const float*)d_in[0]; emb = (const float*)d_in[1]; }
    float* out = (float*)d_out;

    cudaFuncSetAttribute(vq_main, cudaFuncAttributeMaxDynamicSharedMemorySize,
                         SM_TOTAL);

    vq_prep<<<KPAD / 4, 256>>>(emb);
    vq_main<<<NBLK, THREADS, SM_TOTAL>>>(x, emb, out);
}